// round 8
// baseline (speedup 1.0000x reference)
#include <cuda_runtime.h>
#include <cstdint>

// GCN FeatureDiscriminator: B=256, V=512, F=256, O=2
// Round-2 architecture (proven best): A streams, B aggregates, sequential.
// This round: B inner-loop issue-count cuts (LDS.128 masks, lanebit LOP3
// predication, paired-row reduction).

#define BATCH 256
#define BV 512
#define BF 256
#define NROWS (BATCH * BV)
#define NTHREADS 512
#define NWARP 16
#define GRID_A 304
#define TOTAL_WARPS_A (GRID_A * NWARP)

__device__ unsigned g_bits[NROWS * 16];   // 8 MB: 512-bit mask per row
__device__ float    g_dinv[NROWS];
__device__ float2   g_sxw[NROWS];         // dinv[w] * (X[w,:] @ W)

// ---------------------------------------------------------------------------
// Kernel A: warp per row, grid-stride. (unchanged, ~60.5us, 84% of HBM spec)
// Bit convention: bits[row][4c+k] bit 'l'  <->  column w = 128*c + 4*l + k
// ---------------------------------------------------------------------------
__global__ __launch_bounds__(NTHREADS, 2)
void gcn_rows_kernel(const float* __restrict__ features,
                     const int*   __restrict__ graphs,
                     const float* __restrict__ conv_weight)   // [F,2]
{
    const int tid  = threadIdx.x;
    const int wid  = tid >> 5;
    const int lane = tid & 31;
    const int gwarp = blockIdx.x * NWARP + wid;

    float w0r[8], w1r[8];
    {
        const float2* cw2 = (const float2*)conv_weight;
        #pragma unroll
        for (int j = 0; j < 8; j++) {
            float2 w = __ldg(cw2 + 8 * lane + j);
            w0r[j] = w.x; w1r[j] = w.y;
        }
    }

    for (int row = gwarp; row < NROWS; row += TOTAL_WARPS_A) {
        const int v = row & (BV - 1);
        const int4*   grow = (const int4*)graphs + (size_t)row * (BV / 4);
        const float4* frow = (const float4*)features + (size_t)row * (BF / 4);

        int4 x0 = __ldcs(grow + 0 * 32 + lane);
        int4 x1 = __ldcs(grow + 1 * 32 + lane);
        int4 x2 = __ldcs(grow + 2 * 32 + lane);
        int4 x3 = __ldcs(grow + 3 * 32 + lane);
        float4 fa = __ldcs(frow + 2 * lane);
        float4 fb = __ldcs(frow + 2 * lane + 1);

        int deg = 0;
        #pragma unroll
        for (int c = 0; c < 4; c++) {
            int4 x = (c == 0) ? x0 : (c == 1) ? x1 : (c == 2) ? x2 : x3;
            int w0 = 128 * c + 4 * lane;
            unsigned m0 = __ballot_sync(0xffffffffu, (x.x != 0) || (w0     == v));
            unsigned m1 = __ballot_sync(0xffffffffu, (x.y != 0) || (w0 + 1 == v));
            unsigned m2 = __ballot_sync(0xffffffffu, (x.z != 0) || (w0 + 2 == v));
            unsigned m3 = __ballot_sync(0xffffffffu, (x.w != 0) || (w0 + 3 == v));
            deg += __popc(m0) + __popc(m1) + __popc(m2) + __popc(m3);
            if (lane == c) {
                ((uint4*)g_bits)[(size_t)row * 4 + c] = make_uint4(m0, m1, m2, m3);
            }
        }

        float acc0 = fa.x * w0r[0];             float acc1 = fa.x * w1r[0];
        acc0 = fmaf(fa.y, w0r[1], acc0);        acc1 = fmaf(fa.y, w1r[1], acc1);
        acc0 = fmaf(fa.z, w0r[2], acc0);        acc1 = fmaf(fa.z, w1r[2], acc1);
        acc0 = fmaf(fa.w, w0r[3], acc0);        acc1 = fmaf(fa.w, w1r[3], acc1);
        acc0 = fmaf(fb.x, w0r[4], acc0);        acc1 = fmaf(fb.x, w1r[4], acc1);
        acc0 = fmaf(fb.y, w0r[5], acc0);        acc1 = fmaf(fb.y, w1r[5], acc1);
        acc0 = fmaf(fb.z, w0r[6], acc0);        acc1 = fmaf(fb.z, w1r[6], acc1);
        acc0 = fmaf(fb.w, w0r[7], acc0);        acc1 = fmaf(fb.w, w1r[7], acc1);
        #pragma unroll
        for (int s = 16; s; s >>= 1) {
            acc0 += __shfl_xor_sync(0xffffffffu, acc0, s);
            acc1 += __shfl_xor_sync(0xffffffffu, acc1, s);
        }
        if (lane == 0) {
            float d = rsqrtf((float)deg);        // deg >= 1 (self-loop)
            g_dinv[row] = d;
            g_sxw[row]  = make_float2(d * acc0, d * acc1);
        }
    }
}

// ---------------------------------------------------------------------------
// Kernel B: one CTA per batch. Paired-row aggregation.
// ---------------------------------------------------------------------------
__global__ __launch_bounds__(NTHREADS, 2)
void gcn_agg_kernel(const float* __restrict__ conv_bias,
                    const float* __restrict__ lin_weight,   // [2v+o]
                    const float* __restrict__ lin_bias,
                    float* __restrict__ out)
{
    __shared__ unsigned bits[BV][16];   // 32 KB
    __shared__ float s0[BV];
    __shared__ float s1[BV];
    __shared__ float dinv_s[BV];
    __shared__ float lw_s[BV * 2];
    __shared__ float wpart[NWARP * 2];

    const int b    = blockIdx.x;
    const int tid  = threadIdx.x;
    const int wid  = tid >> 5;
    const int lane = tid & 31;
    const unsigned lanebit = 1u << lane;

    {
        const uint4* src = (const uint4*)g_bits + (size_t)b * (BV * 4);
        uint4* dst = (uint4*)bits;
        #pragma unroll
        for (int i = 0; i < 4; i++) dst[tid + i * NTHREADS] = src[tid + i * NTHREADS];

        float2 xw = g_sxw[b * BV + tid];           // already dinv-scaled
        s0[tid] = xw.x;
        s1[tid] = xw.y;
        dinv_s[tid] = g_dinv[b * BV + tid];

        lw_s[tid]            = lin_weight[tid];
        lw_s[tid + NTHREADS] = lin_weight[tid + NTHREADS];
    }
    __syncthreads();

    // preload this lane's fixed 16 s pairs: w = 128*c + 4*lane + k
    float r0[16], r1[16];
    #pragma unroll
    for (int c = 0; c < 4; c++)
        #pragma unroll
        for (int k = 0; k < 4; k++) {
            int w = 128 * c + 4 * lane + k;
            r0[4 * c + k] = s0[w];
            r1[4 * c + k] = s1[w];
        }

    const float cb0 = conv_bias[0];
    const float cb1 = conv_bias[1];
    const bool hi_half = (lane & 16);

    float part = 0.0f;
    #pragma unroll 2
    for (int rp = 0; rp < 16; rp++) {              // 16 row-pairs per warp
        const int vA = wid * 32 + 2 * rp;
        const int vB = vA + 1;

        // row A: 4 broadcast LDS.128, lanebit-predicated accumulate
        const uint4* bwA = (const uint4*)bits[vA];
        float a0 = 0.0f, a1 = 0.0f;
        #pragma unroll
        for (int c = 0; c < 4; c++) {
            uint4 q = bwA[c];
            if (q.x & lanebit) { a0 += r0[4*c+0]; a1 += r1[4*c+0]; }
            if (q.y & lanebit) { a0 += r0[4*c+1]; a1 += r1[4*c+1]; }
            if (q.z & lanebit) { a0 += r0[4*c+2]; a1 += r1[4*c+2]; }
            if (q.w & lanebit) { a0 += r0[4*c+3]; a1 += r1[4*c+3]; }
        }

        // row B
        const uint4* bwB = (const uint4*)bits[vB];
        float b0 = 0.0f, b1 = 0.0f;
        #pragma unroll
        for (int c = 0; c < 4; c++) {
            uint4 q = bwB[c];
            if (q.x & lanebit) { b0 += r0[4*c+0]; b1 += r1[4*c+0]; }
            if (q.y & lanebit) { b0 += r0[4*c+1]; b1 += r1[4*c+1]; }
            if (q.z & lanebit) { b0 += r0[4*c+2]; b1 += r1[4*c+2]; }
            if (q.w & lanebit) { b0 += r0[4*c+3]; b1 += r1[4*c+3]; }
        }

        // paired reduction: fold 16, select halves, 4-level butterfly
        a0 += __shfl_xor_sync(0xffffffffu, a0, 16);
        a1 += __shfl_xor_sync(0xffffffffu, a1, 16);
        b0 += __shfl_xor_sync(0xffffffffu, b0, 16);
        b1 += __shfl_xor_sync(0xffffffffu, b1, 16);
        float c0 = hi_half ? b0 : a0;
        float c1 = hi_half ? b1 : a1;
        #pragma unroll
        for (int s = 8; s; s >>= 1) {
            c0 += __shfl_xor_sync(0xffffffffu, c0, s);
            c1 += __shfl_xor_sync(0xffffffffu, c1, s);
        }

        // epilogue on lanes 0 (row A) and 16 (row B)
        if ((lane & 15) == 0) {
            const int v = hi_half ? vB : vA;
            float d  = dinv_s[v];
            float h0 = fmaxf(fmaf(d, c0, cb0), 0.0f);
            float h1 = fmaxf(fmaf(d, c1, cb1), 0.0f);
            part = fmaf(h0, lw_s[2 * v], part);
            part = fmaf(h1, lw_s[2 * v + 1], part);
        }
    }
    if ((lane & 15) == 0) wpart[wid * 2 + (hi_half ? 1 : 0)] = part;
    __syncthreads();

    if (wid == 0) {
        float sdot = wpart[lane];                  // exactly 32 partials
        #pragma unroll
        for (int sh = 16; sh; sh >>= 1)
            sdot += __shfl_xor_sync(0xffffffffu, sdot, sh);
        if (lane == 0) {
            float logit = sdot + lin_bias[0];
            out[b] = 1.0f / (1.0f + expf(-logit));
        }
    }
}

extern "C" void kernel_launch(void* const* d_in, const int* in_sizes, int n_in,
                              void* d_out, int out_size) {
    const float* features    = (const float*)d_in[0];
    const int*   graphs      = (const int*)  d_in[1];
    const float* conv_weight = (const float*)d_in[2];
    const float* conv_bias   = (const float*)d_in[3];
    const float* lin_weight  = (const float*)d_in[4];
    const float* lin_bias    = (const float*)d_in[5];
    float* out = (float*)d_out;

    gcn_rows_kernel<<<GRID_A, NTHREADS>>>(features, graphs, conv_weight);
    gcn_agg_kernel<<<BATCH, NTHREADS>>>(conv_bias, lin_weight, lin_bias, out);
}

// round 10
// speedup vs baseline: 1.1050x; 1.1050x over previous
#include <cuda_runtime.h>
#include <cstdint>

// GCN FeatureDiscriminator: B=256, V=512, F=256, O=2
// Architecture (proven): A streams graphs+features -> bits/dinv/sxw; B aggregates.
// Round 10 = Round 9 minus redux.f32 (not supported on sm_103): shfl butterfly
// reduction, keeping lanebit single-LOP3 predication + quarter-batch occ-8 CTAs.

#define BATCH 256
#define BV 512
#define BF 256
#define NROWS (BATCH * BV)
#define NTHREADS 512
#define NWARP 16
#define GRID_A 304
#define TOTAL_WARPS_A (GRID_A * NWARP)
#define QROWS 128                     // rows per B CTA (quarter batch)

__device__ unsigned g_bits[NROWS * 16];   // 8 MB: 512-bit mask per row
__device__ float    g_dinv[NROWS];
__device__ float2   g_sxw[NROWS];         // dinv[w] * (X[w,:] @ W)
__device__ float    g_part[BATCH * 4];    // per-quarter head partials

// ---------------------------------------------------------------------------
// Kernel A: warp per row, grid-stride. (unchanged — proven ~60.5us)
// Bit convention: bits[row][4c+k] bit 'l'  <->  column w = 128*c + 4*l + k
// ---------------------------------------------------------------------------
__global__ __launch_bounds__(NTHREADS, 2)
void gcn_rows_kernel(const float* __restrict__ features,
                     const int*   __restrict__ graphs,
                     const float* __restrict__ conv_weight)   // [F,2]
{
    const int tid  = threadIdx.x;
    const int wid  = tid >> 5;
    const int lane = tid & 31;
    const int gwarp = blockIdx.x * NWARP + wid;

    float w0r[8], w1r[8];
    {
        const float2* cw2 = (const float2*)conv_weight;
        #pragma unroll
        for (int j = 0; j < 8; j++) {
            float2 w = __ldg(cw2 + 8 * lane + j);
            w0r[j] = w.x; w1r[j] = w.y;
        }
    }

    for (int row = gwarp; row < NROWS; row += TOTAL_WARPS_A) {
        const int v = row & (BV - 1);
        const int4*   grow = (const int4*)graphs + (size_t)row * (BV / 4);
        const float4* frow = (const float4*)features + (size_t)row * (BF / 4);

        int4 x0 = __ldcs(grow + 0 * 32 + lane);
        int4 x1 = __ldcs(grow + 1 * 32 + lane);
        int4 x2 = __ldcs(grow + 2 * 32 + lane);
        int4 x3 = __ldcs(grow + 3 * 32 + lane);
        float4 fa = __ldcs(frow + 2 * lane);
        float4 fb = __ldcs(frow + 2 * lane + 1);

        int deg = 0;
        #pragma unroll
        for (int c = 0; c < 4; c++) {
            int4 x = (c == 0) ? x0 : (c == 1) ? x1 : (c == 2) ? x2 : x3;
            int w0 = 128 * c + 4 * lane;
            unsigned m0 = __ballot_sync(0xffffffffu, (x.x != 0) || (w0     == v));
            unsigned m1 = __ballot_sync(0xffffffffu, (x.y != 0) || (w0 + 1 == v));
            unsigned m2 = __ballot_sync(0xffffffffu, (x.z != 0) || (w0 + 2 == v));
            unsigned m3 = __ballot_sync(0xffffffffu, (x.w != 0) || (w0 + 3 == v));
            deg += __popc(m0) + __popc(m1) + __popc(m2) + __popc(m3);
            if (lane == c) {
                ((uint4*)g_bits)[(size_t)row * 4 + c] = make_uint4(m0, m1, m2, m3);
            }
        }

        float acc0 = fa.x * w0r[0];             float acc1 = fa.x * w1r[0];
        acc0 = fmaf(fa.y, w0r[1], acc0);        acc1 = fmaf(fa.y, w1r[1], acc1);
        acc0 = fmaf(fa.z, w0r[2], acc0);        acc1 = fmaf(fa.z, w1r[2], acc1);
        acc0 = fmaf(fa.w, w0r[3], acc0);        acc1 = fmaf(fa.w, w1r[3], acc1);
        acc0 = fmaf(fb.x, w0r[4], acc0);        acc1 = fmaf(fb.x, w1r[4], acc1);
        acc0 = fmaf(fb.y, w0r[5], acc0);        acc1 = fmaf(fb.y, w1r[5], acc1);
        acc0 = fmaf(fb.z, w0r[6], acc0);        acc1 = fmaf(fb.z, w1r[6], acc1);
        acc0 = fmaf(fb.w, w0r[7], acc0);        acc1 = fmaf(fb.w, w1r[7], acc1);
        #pragma unroll
        for (int s = 16; s; s >>= 1) {
            acc0 += __shfl_xor_sync(0xffffffffu, acc0, s);
            acc1 += __shfl_xor_sync(0xffffffffu, acc1, s);
        }
        if (lane == 0) {
            float d = rsqrtf((float)deg);        // deg >= 1 (self-loop)
            g_dinv[row] = d;
            g_sxw[row]  = make_float2(d * acc0, d * acc1);
        }
    }
}

// ---------------------------------------------------------------------------
// Kernel B: quarter-batch per CTA. 1024 CTAs x 128 threads, occ 8.
// blockIdx.x = 4*b + q ; rows [128q, 128q+128) of batch b.
// ---------------------------------------------------------------------------
__global__ __launch_bounds__(128, 8)
void gcn_agg_kernel(const float* __restrict__ conv_bias,
                    const float* __restrict__ lin_weight)    // [2v+o]
{
    __shared__ unsigned bits[QROWS][16];   // 8 KB
    __shared__ float s0[BV];               // 2 KB
    __shared__ float s1[BV];               // 2 KB
    __shared__ float dinv_s[QROWS];        // 0.5 KB
    __shared__ float2 lw2[QROWS];          // 1 KB
    __shared__ float wpart[4];

    const int b    = blockIdx.x >> 2;
    const int q    = blockIdx.x & 3;
    const int tid  = threadIdx.x;
    const int wid  = tid >> 5;             // 0..3
    const int lane = tid & 31;
    const unsigned lanebit = 1u << lane;

    // ---- stage (coalesced) ----
    {
        const uint4* src = (const uint4*)g_bits + (size_t)b * (BV * 4)
                         + (size_t)q * (QROWS * 4);
        #pragma unroll
        for (int i = 0; i < 4; i++)
            ((uint4*)bits)[tid + i * 128] = src[tid + i * 128];

        #pragma unroll
        for (int i = 0; i < 4; i++) {
            float2 t = g_sxw[b * BV + tid + i * 128];   // already dinv-scaled
            s0[tid + i * 128] = t.x;
            s1[tid + i * 128] = t.y;
        }
        dinv_s[tid] = g_dinv[b * BV + q * QROWS + tid];
        lw2[tid]    = ((const float2*)lin_weight)[q * QROWS + tid];
    }
    __syncthreads();

    // preload this lane's fixed 16 s pairs: w = 128*c + 4*lane + k
    float r0[16], r1[16];
    #pragma unroll
    for (int c = 0; c < 4; c++)
        #pragma unroll
        for (int k = 0; k < 4; k++) {
            int w = 128 * c + 4 * lane + k;
            r0[4 * c + k] = s0[w];
            r1[4 * c + k] = s1[w];
        }

    const float cb0 = conv_bias[0];
    const float cb1 = conv_bias[1];

    float part = 0.0f;
    #pragma unroll 2
    for (int r = 0; r < QROWS / 4; r++) {          // 32 rows per warp
        const int v = (wid << 5) + r;              // local row
        float acc0 = 0.0f, acc1 = 0.0f;
        #pragma unroll
        for (int j = 0; j < 16; j++) {
            unsigned m = bits[v][j];               // broadcast LDS
            if (m & lanebit) {                     // single LOP3 -> pred
                acc0 += r0[j];
                acc1 += r1[j];
            }
        }
        #pragma unroll
        for (int s = 16; s; s >>= 1) {
            acc0 += __shfl_xor_sync(0xffffffffu, acc0, s);
            acc1 += __shfl_xor_sync(0xffffffffu, acc1, s);
        }
        if (lane == 0) {
            float d   = dinv_s[v];
            float2 lw = lw2[v];
            float h0 = fmaxf(fmaf(d, acc0, cb0), 0.0f);
            float h1 = fmaxf(fmaf(d, acc1, cb1), 0.0f);
            part = fmaf(h0, lw.x, part);
            part = fmaf(h1, lw.y, part);
        }
    }
    if (lane == 0) wpart[wid] = part;
    __syncthreads();

    if (tid == 0)
        g_part[blockIdx.x] = (wpart[0] + wpart[1]) + (wpart[2] + wpart[3]);
}

// ---------------------------------------------------------------------------
// Final: sum 4 quarter-partials per batch + bias, sigmoid.
// ---------------------------------------------------------------------------
__global__ void gcn_fin_kernel(const float* __restrict__ lin_bias,
                               float* __restrict__ out)
{
    int b = threadIdx.x;
    float4 p = ((const float4*)g_part)[b];
    float logit = (p.x + p.y) + (p.z + p.w) + lin_bias[0];
    out[b] = 1.0f / (1.0f + expf(-logit));
}

extern "C" void kernel_launch(void* const* d_in, const int* in_sizes, int n_in,
                              void* d_out, int out_size) {
    const float* features    = (const float*)d_in[0];
    const int*   graphs      = (const int*)  d_in[1];
    const float* conv_weight = (const float*)d_in[2];
    const float* conv_bias   = (const float*)d_in[3];
    const float* lin_weight  = (const float*)d_in[4];
    const float* lin_bias    = (const float*)d_in[5];
    float* out = (float*)d_out;

    gcn_rows_kernel<<<GRID_A, NTHREADS>>>(features, graphs, conv_weight);
    gcn_agg_kernel<<<BATCH * 4, 128>>>(conv_bias, lin_weight);
    gcn_fin_kernel<<<1, BATCH>>>(lin_bias, out);
}